// round 2
// baseline (speedup 1.0000x reference)
#include <cuda_runtime.h>

#define NUM_JOINT 19
#define ROOT_SCALE 200.0f
#define BLOCK 128
#define STRIDE 84            // floats per smem row (16B aligned, LDS.128 conflict-free)

__global__ __launch_bounds__(BLOCK, 4)
void fk_kernel(const float* __restrict__ root,
               const float* __restrict__ joint,
               const float* __restrict__ offsets,
               float* __restrict__ out)
{
    __shared__ float s[BLOCK * STRIDE];
    const int t = threadIdx.x;

    // Coalesced float4 stage-in: BLOCK*19 float4s per block.
    const float4* joint4 = (const float4*)joint + (long long)blockIdx.x * (BLOCK * NUM_JOINT);
    #pragma unroll
    for (int i = 0; i < NUM_JOINT; i++) {
        int idx4 = t + i * BLOCK;              // 0 .. BLOCK*19-1
        int r = idx4 / NUM_JOINT;              // const-div -> mul/shift
        int c = idx4 % NUM_JOINT;
        float4 v = joint4[idx4];
        *(float4*)&s[r * STRIDE + c * 4] = v;
    }
    __syncthreads();

    const int b = blockIdx.x * BLOCK + t;
    const float rx = root[b * 3 + 0] * ROOT_SCALE;
    const float ry = root[b * 3 + 1] * ROOT_SCALE;
    const float rz = root[b * 3 + 2] * ROOT_SCALE;

    float Rm[NUM_JOINT][9];
    float pm[NUM_JOINT][3];
    const int parents[NUM_JOINT] = {-1,0,1,2,3,2,5,6,7,2,9,10,11,0,13,14,0,16,17};
    const float* row = &s[t * STRIDE];
    float4* out4 = (float4*)out + (long long)b * NUM_JOINT;

    #pragma unroll
    for (int j = 0; j < NUM_JOINT; j++) {
        const float4 q = *(const float4*)&row[j * 4];
        const float w = q.x, x = q.y, y = q.z, z = q.w;
        const float ts = 2.0f / (w * w + x * x + y * y + z * z);

        float R[9];
        R[0] = 1.0f - ts * (y * y + z * z);
        R[1] = ts * (x * y - z * w);
        R[2] = ts * (x * z + y * w);
        R[3] = ts * (x * y + z * w);
        R[4] = 1.0f - ts * (x * x + z * z);
        R[5] = ts * (y * z - x * w);
        R[6] = ts * (x * z - y * w);
        R[7] = ts * (y * z + x * w);
        R[8] = 1.0f - ts * (x * x + y * y);

        // offsets = identity rotation + translation t_j  => RT = [R | R*t_j]
        const float tx = __ldg(&offsets[j * 16 + 3]);
        const float ty = __ldg(&offsets[j * 16 + 7]);
        const float tz = __ldg(&offsets[j * 16 + 11]);
        const float plx = R[0] * tx + R[1] * ty + R[2] * tz;
        const float ply = R[3] * tx + R[4] * ty + R[5] * tz;
        const float plz = R[6] * tx + R[7] * ty + R[8] * tz;

        if (j == 0) {
            #pragma unroll
            for (int k = 0; k < 9; k++) Rm[0][k] = R[k];
            pm[0][0] = plx; pm[0][1] = ply; pm[0][2] = plz;
        } else {
            const int p = parents[j];
            #pragma unroll
            for (int r = 0; r < 3; r++) {
                #pragma unroll
                for (int c = 0; c < 3; c++) {
                    Rm[j][r * 3 + c] = Rm[p][r * 3 + 0] * R[0 + c]
                                     + Rm[p][r * 3 + 1] * R[3 + c]
                                     + Rm[p][r * 3 + 2] * R[6 + c];
                }
            }
            pm[j][0] = Rm[p][0] * plx + Rm[p][1] * ply + Rm[p][2] * plz + pm[p][0];
            pm[j][1] = Rm[p][3] * plx + Rm[p][4] * ply + Rm[p][5] * plz + pm[p][1];
            pm[j][2] = Rm[p][6] * plx + Rm[p][7] * ply + Rm[p][8] * plz + pm[p][2];
        }

        // Store position j immediately (contiguous 304B per thread; L2 write-back
        // assembles full lines, so DRAM sees coalesced traffic).
        float4 o;
        o.x = pm[j][0] + rx;
        o.y = pm[j][1] + ry;
        o.z = pm[j][2] + rz;
        o.w = 1.0f;
        out4[j] = o;
    }
}

extern "C" void kernel_launch(void* const* d_in, const int* in_sizes, int n_in,
                              void* d_out, int out_size)
{
    const float* root    = (const float*)d_in[0];   // (B, 3)
    const float* joint   = (const float*)d_in[1];   // (B, 76)
    const float* offsets = (const float*)d_in[2];   // (19, 4, 4)
    float* out = (float*)d_out;                     // (B, 19, 4)

    const int B = in_sizes[1] / (NUM_JOINT * 4);
    const int grid = (B + BLOCK - 1) / BLOCK;
    fk_kernel<<<grid, BLOCK>>>(root, joint, offsets, out);
}

// round 3
// speedup vs baseline: 1.4207x; 1.4207x over previous
#include <cuda_runtime.h>

#define NUM_JOINT 19
#define ROOT_SCALE 200.0f
#define BLOCK 128
#define STRIDE 84            // floats per smem row (16B aligned; LDS.128 conflict-free)

__global__ __launch_bounds__(BLOCK, 5)
void fk_kernel(const float* __restrict__ root,
               const float* __restrict__ joint,
               const float* __restrict__ offsets,
               float* __restrict__ out)
{
    __shared__ float s[BLOCK * STRIDE];
    const int t = threadIdx.x;

    // ---- Coalesced float4 stage-in: BLOCK*19 float4s per block ----
    const float4* joint4 = (const float4*)joint + (long long)blockIdx.x * (BLOCK * NUM_JOINT);
    #pragma unroll
    for (int i = 0; i < NUM_JOINT; i++) {
        int idx4 = t + i * BLOCK;
        int r = idx4 / NUM_JOINT;
        int c = idx4 % NUM_JOINT;
        *(float4*)&s[r * STRIDE + c * 4] = joint4[idx4];
    }
    __syncthreads();

    const int b = blockIdx.x * BLOCK + t;
    const float rx = root[b * 3 + 0] * ROOT_SCALE;
    const float ry = root[b * 3 + 1] * ROOT_SCALE;
    const float rz = root[b * 3 + 2] * ROOT_SCALE;

    // Composite (non-unit) quaternion per joint: R(g_p (x) q_j) = R(g_p) R(q_j).
    float gw[NUM_JOINT], gx[NUM_JOINT], gy[NUM_JOINT], gz[NUM_JOINT];
    float px[NUM_JOINT], py[NUM_JOINT], pz[NUM_JOINT];
    const int parents[NUM_JOINT] = {-1,0,1,2,3,2,5,6,7,2,9,10,11,0,13,14,0,16,17};
    float* row = &s[t * STRIDE];

    #pragma unroll
    for (int j = 0; j < NUM_JOINT; j++) {
        const float4 q = *(const float4*)&row[j * 4];
        float aw, ax, ay, az;
        if (j == 0) {
            aw = q.x; ax = q.y; ay = q.z; az = q.w;
        } else {
            const int p = parents[j];
            const float bw = q.x, bx = q.y, by = q.z, bz = q.w;
            aw = gw[p]*bw - gx[p]*bx - gy[p]*by - gz[p]*bz;
            ax = gw[p]*bx + gx[p]*bw + gy[p]*bz - gz[p]*by;
            ay = gw[p]*by - gx[p]*bz + gy[p]*bw + gz[p]*bx;
            az = gw[p]*bz + gx[p]*by - gy[p]*bx + gz[p]*bw;
        }
        gw[j] = aw; gx[j] = ax; gy[j] = ay; gz[j] = az;

        // Rotate translation t_j by composite quat: v' = s*(aw*c + a x c), c = a x T
        const float tx = __ldg(&offsets[j * 16 + 3]);
        const float ty = __ldg(&offsets[j * 16 + 7]);
        const float tz = __ldg(&offsets[j * 16 + 11]);

        const float n = aw*aw + ax*ax + ay*ay + az*az;
        const float sc = __fdividef(2.0f, n);

        const float cx = ay*tz - az*ty;
        const float cy = az*tx - ax*tz;
        const float cz = ax*ty - ay*tx;

        const float dx = aw*cx + (ay*cz - az*cy);
        const float dy = aw*cy + (az*cx - ax*cz);
        const float dz = aw*cz + (ax*cy - ay*cx);

        float ox = tx + sc * dx;
        float oy = ty + sc * dy;
        float oz = tz + sc * dz;
        if (j > 0) {
            const int p = parents[j];
            ox += px[p]; oy += py[p]; oz += pz[p];
        }
        px[j] = ox; py[j] = oy; pz[j] = oz;

        // In-place: position j (xyz + scaled root, w=1) overwrites quat j in smem.
        float4 o;
        o.x = ox + rx; o.y = oy + ry; o.z = oz + rz; o.w = 1.0f;
        *(float4*)&row[j * 4] = o;
    }
    __syncthreads();

    // ---- Coalesced float4 stage-out ----
    float4* out4 = (float4*)out + (long long)blockIdx.x * (BLOCK * NUM_JOINT);
    #pragma unroll
    for (int i = 0; i < NUM_JOINT; i++) {
        int idx4 = t + i * BLOCK;
        int r = idx4 / NUM_JOINT;
        int c = idx4 % NUM_JOINT;
        out4[idx4] = *(float4*)&s[r * STRIDE + c * 4];
    }
}

extern "C" void kernel_launch(void* const* d_in, const int* in_sizes, int n_in,
                              void* d_out, int out_size)
{
    const float* root    = (const float*)d_in[0];   // (B, 3)
    const float* joint   = (const float*)d_in[1];   // (B, 76)
    const float* offsets = (const float*)d_in[2];   // (19, 4, 4)
    float* out = (float*)d_out;                     // (B, 19, 4)

    const int B = in_sizes[1] / (NUM_JOINT * 4);
    const int grid = (B + BLOCK - 1) / BLOCK;
    fk_kernel<<<grid, BLOCK>>>(root, joint, offsets, out);
}

// round 4
// speedup vs baseline: 1.6150x; 1.1368x over previous
#include <cuda_runtime.h>

#define NUM_JOINT 19
#define ROOT_SCALE 200.0f
#define BLOCK 64
#define STRIDE 76   // == ROWLEN: no padding; 76-float stride is LDS.128 conflict-free
                    // (phase bank starts {0,12,24,4,16,28,8,20} tile all 32 banks)

__global__ __launch_bounds__(BLOCK, 11)
void fk_kernel(const float* __restrict__ root,
               const float* __restrict__ joint,
               const float* __restrict__ offsets,
               float* __restrict__ out)
{
    __shared__ float s[BLOCK * STRIDE];        // 19456 B
    float4* s4 = (float4*)s;
    const int t = threadIdx.x;

    // ---- Stage-in: smem layout == global layout -> zero address math ----
    const float4* joint4 = (const float4*)joint + (long long)blockIdx.x * (BLOCK * NUM_JOINT);
    #pragma unroll
    for (int i = 0; i < NUM_JOINT; i++) {
        int idx = t + i * BLOCK;
        s4[idx] = joint4[idx];
    }
    __syncthreads();

    const int b = blockIdx.x * BLOCK + t;
    const float rx = root[b * 3 + 0] * ROOT_SCALE;
    const float ry = root[b * 3 + 1] * ROOT_SCALE;
    const float rz = root[b * 3 + 2] * ROOT_SCALE;

    // Composite (non-unit) quaternion per joint: R(g_p (x) q_j) = R(g_p) R(q_j).
    float gw[NUM_JOINT], gx[NUM_JOINT], gy[NUM_JOINT], gz[NUM_JOINT];
    float px[NUM_JOINT], py[NUM_JOINT], pz[NUM_JOINT];
    const int parents[NUM_JOINT] = {-1,0,1,2,3,2,5,6,7,2,9,10,11,0,13,14,0,16,17};
    float* row = &s[t * STRIDE];

    #pragma unroll
    for (int j = 0; j < NUM_JOINT; j++) {
        const float4 q = *(const float4*)&row[j * 4];
        float aw, ax, ay, az;
        if (j == 0) {
            aw = q.x; ax = q.y; ay = q.z; az = q.w;
        } else {
            const int p = parents[j];
            const float bw = q.x, bx = q.y, by = q.z, bz = q.w;
            aw = gw[p]*bw - gx[p]*bx - gy[p]*by - gz[p]*bz;
            ax = gw[p]*bx + gx[p]*bw + gy[p]*bz - gz[p]*by;
            ay = gw[p]*by - gx[p]*bz + gy[p]*bw + gz[p]*bx;
            az = gw[p]*bz + gx[p]*by - gy[p]*bx + gz[p]*bw;
        }
        gw[j] = aw; gx[j] = ax; gy[j] = ay; gz[j] = az;

        // Rotate translation t_j by composite quat: o = t + (2/|g|^2)*(aw*c + a x c), c = a x t
        const float tx = __ldg(&offsets[j * 16 + 3]);
        const float ty = __ldg(&offsets[j * 16 + 7]);
        const float tz = __ldg(&offsets[j * 16 + 11]);

        const float n  = aw*aw + ax*ax + ay*ay + az*az;
        const float sc = __fdividef(2.0f, n);

        const float cx = ay*tz - az*ty;
        const float cy = az*tx - ax*tz;
        const float cz = ax*ty - ay*tx;

        const float dx = aw*cx + (ay*cz - az*cy);
        const float dy = aw*cy + (az*cx - ax*cz);
        const float dz = aw*cz + (ax*cy - ay*cx);

        float ox = tx + sc * dx;
        float oy = ty + sc * dy;
        float oz = tz + sc * dz;
        if (j > 0) {
            const int p = parents[j];
            ox += px[p]; oy += py[p]; oz += pz[p];
        }
        px[j] = ox; py[j] = oy; pz[j] = oz;

        // In-place: position j (xyz + scaled root, w=1) overwrites quat j in smem.
        float4 o;
        o.x = ox + rx; o.y = oy + ry; o.z = oz + rz; o.w = 1.0f;
        *(float4*)&row[j * 4] = o;
    }
    __syncthreads();

    // ---- Stage-out: identical linear mapping ----
    float4* out4 = (float4*)out + (long long)blockIdx.x * (BLOCK * NUM_JOINT);
    #pragma unroll
    for (int i = 0; i < NUM_JOINT; i++) {
        int idx = t + i * BLOCK;
        out4[idx] = s4[idx];
    }
}

extern "C" void kernel_launch(void* const* d_in, const int* in_sizes, int n_in,
                              void* d_out, int out_size)
{
    const float* root    = (const float*)d_in[0];   // (B, 3)
    const float* joint   = (const float*)d_in[1];   // (B, 76)
    const float* offsets = (const float*)d_in[2];   // (19, 4, 4)
    float* out = (float*)d_out;                     // (B, 19, 4)

    const int B = in_sizes[1] / (NUM_JOINT * 4);
    const int grid = (B + BLOCK - 1) / BLOCK;
    fk_kernel<<<grid, BLOCK>>>(root, joint, offsets, out);
}

// round 5
// speedup vs baseline: 1.7395x; 1.0771x over previous
#include <cuda_runtime.h>
#include <cstdint>

#define NUM_JOINT 19
#define ROOT_SCALE 200.0f
#define BLOCK 32
#define TILE_BYTES (BLOCK * NUM_JOINT * 16)   // 9728

__constant__ float c_off[NUM_JOINT * 16];

__global__ __launch_bounds__(BLOCK, 20)
void fk_kernel(const float* __restrict__ root,
               const float* __restrict__ joint,
               float* __restrict__ out)
{
    __shared__ alignas(16) float s[BLOCK * NUM_JOINT * 4];
    __shared__ alignas(8) unsigned long long mbar;

    const int t = threadIdx.x;
    const uint32_t s_addr    = (uint32_t)__cvta_generic_to_shared(s);
    const uint32_t mbar_addr = (uint32_t)__cvta_generic_to_shared(&mbar);

    if (t == 0)
        asm volatile("mbarrier.init.shared.b64 [%0], 1;" :: "r"(mbar_addr) : "memory");
    __syncwarp();

    // One bulk async copy stages the whole CTA tile (gmem -> smem, same layout).
    const float* gsrc = joint + (size_t)blockIdx.x * (BLOCK * NUM_JOINT * 4);
    if (t == 0) {
        asm volatile("mbarrier.arrive.expect_tx.shared.b64 _, [%0], %1;"
                     :: "r"(mbar_addr), "r"((uint32_t)TILE_BYTES) : "memory");
        asm volatile("cp.async.bulk.shared::cta.global.mbarrier::complete_tx::bytes "
                     "[%0], [%1], %2, [%3];"
                     :: "r"(s_addr), "l"(gsrc), "r"((uint32_t)TILE_BYTES), "r"(mbar_addr)
                     : "memory");
    }

    // Overlap the bulk load with the root fetch.
    const int b = blockIdx.x * BLOCK + t;
    const float rx = __ldg(&root[b * 3 + 0]) * ROOT_SCALE;
    const float ry = __ldg(&root[b * 3 + 1]) * ROOT_SCALE;
    const float rz = __ldg(&root[b * 3 + 2]) * ROOT_SCALE;

    // Wait for tile (phase parity 0).
    asm volatile(
        "{\n\t.reg .pred P;\n\t"
        "W%=:\n\t"
        "mbarrier.try_wait.parity.acquire.cta.shared::cta.b64 P, [%0], 0;\n\t"
        "@!P bra W%=;\n\t}"
        :: "r"(mbar_addr) : "memory");

    // Composite (non-unit) quaternion chain: R(g_p (x) q_j) = R(g_p) R(q_j).
    float gw[NUM_JOINT], gx[NUM_JOINT], gy[NUM_JOINT], gz[NUM_JOINT];
    float px[NUM_JOINT], py[NUM_JOINT], pz[NUM_JOINT];
    const int parents[NUM_JOINT] = {-1,0,1,2,3,2,5,6,7,2,9,10,11,0,13,14,0,16,17};
    float* row = &s[t * (NUM_JOINT * 4)];   // 76-float stride: LDS.128 conflict-free

    #pragma unroll
    for (int j = 0; j < NUM_JOINT; j++) {
        const float4 q = *(const float4*)&row[j * 4];
        float aw, ax, ay, az;
        if (j == 0) {
            aw = q.x; ax = q.y; ay = q.z; az = q.w;
        } else {
            const int p = parents[j];
            const float bw = q.x, bx = q.y, by = q.z, bz = q.w;
            aw = gw[p]*bw - gx[p]*bx - gy[p]*by - gz[p]*bz;
            ax = gw[p]*bx + gx[p]*bw + gy[p]*bz - gz[p]*by;
            ay = gw[p]*by - gx[p]*bz + gy[p]*bw + gz[p]*bx;
            az = gw[p]*bz + gx[p]*by - gy[p]*bx + gz[p]*bw;
        }
        gw[j] = aw; gx[j] = ax; gy[j] = ay; gz[j] = az;

        // o = t + (2/|g|^2) * (aw*c + g x c),  c = g x t   (t from constant bank)
        const float tx = c_off[j * 16 + 3];
        const float ty = c_off[j * 16 + 7];
        const float tz = c_off[j * 16 + 11];

        const float n  = aw*aw + ax*ax + ay*ay + az*az;
        const float sc = __fdividef(2.0f, n);

        const float cx = ay*tz - az*ty;
        const float cy = az*tx - ax*tz;
        const float cz = ax*ty - ay*tx;

        const float dx = aw*cx + (ay*cz - az*cy);
        const float dy = aw*cy + (az*cx - ax*cz);
        const float dz = aw*cz + (ax*cy - ay*cx);

        float ox = tx + sc * dx;
        float oy = ty + sc * dy;
        float oz = tz + sc * dz;
        if (j > 0) {
            const int p = parents[j];
            ox += px[p]; oy += py[p]; oz += pz[p];
        }
        px[j] = ox; py[j] = oy; pz[j] = oz;

        // In-place: position j (xyz + scaled root, w=1) overwrites quat j.
        float4 o;
        o.x = ox + rx; o.y = oy + ry; o.z = oz + rz; o.w = 1.0f;
        *(float4*)&row[j * 4] = o;
    }
    __syncwarp();

    // One bulk async store for the whole tile (smem -> gmem, same layout).
    if (t == 0) {
        asm volatile("fence.proxy.async.shared::cta;" ::: "memory");
        float* gdst = out + (size_t)blockIdx.x * (BLOCK * NUM_JOINT * 4);
        asm volatile("cp.async.bulk.global.shared::cta.bulk_group [%0], [%1], %2;"
                     :: "l"(gdst), "r"(s_addr), "r"((uint32_t)TILE_BYTES) : "memory");
        asm volatile("cp.async.bulk.commit_group;" ::: "memory");
        asm volatile("cp.async.bulk.wait_group 0;" ::: "memory");
    }
}

extern "C" void kernel_launch(void* const* d_in, const int* in_sizes, int n_in,
                              void* d_out, int out_size)
{
    const float* root    = (const float*)d_in[0];   // (B, 3)
    const float* joint   = (const float*)d_in[1];   // (B, 76)
    const float* offsets = (const float*)d_in[2];   // (19, 4, 4)
    float* out = (float*)d_out;                     // (B, 19, 4)

    // 304B of offsets -> constant bank (graph-capturable async memcpy node).
    cudaMemcpyToSymbolAsync(c_off, offsets, NUM_JOINT * 16 * sizeof(float),
                            0, cudaMemcpyDeviceToDevice, 0);

    const int B = in_sizes[1] / (NUM_JOINT * 4);
    const int grid = (B + BLOCK - 1) / BLOCK;
    fk_kernel<<<grid, BLOCK>>>(root, joint, out);
}